// round 9
// baseline (speedup 1.0000x reference)
#include <cuda_runtime.h>
#include <cuda_bf16.h>

#define BS   128
#define OBJ  512
#define RNN  1024
#define HID  512
#define KCHUNKS 16   // k-chunks of 64

// GEMM partials, layout [chunk][hid][bs] -> coalesced stores. 4MB, L2-resident.
__device__ float g_part[KCHUNKS * HID * BS];
// Reduced att_h + bias, layout [hid][bs] (256KB, L2-resident).
__device__ float g_atth[HID * BS];
// Masked un-normalized exp values + per-(row,chunk) partial sums.
__device__ float g_e[BS * OBJ];
__device__ float g_psum[BS * 4];
// Arrival counters (zero-init; reset after use -> graph-replay safe).
__device__ int g_cntn[16];
__device__ int g_cntb[BS];

__device__ __forceinline__ float tanh_fast(float x) {
    float y;
    asm("tanh.approx.f32 %0, %1;" : "=f"(y) : "f"(x));
    return y;
}

// ---------------- K1: GEMM partials + fused chunk-reduce tail ----------------
// grid (16 n-tiles of 32, 16 k-chunks of 64), 256 threads, 2 pipelined
// k-stages (R4-proven core). part[c][n][b] = sum_{k in c} h[b][k]*W[n][k].
// The 16th block per n-tile sums all 16 chunks + bias into g_atth.
__global__ __launch_bounds__(256) void gemm_kernel(
    const float* __restrict__ h, const float* __restrict__ W,
    const float* __restrict__ b_h2att)
{
    __shared__ float h_s[32][129];
    __shared__ float w_s[32][33];
    __shared__ int   lastFlag;
    const int n0 = blockIdx.x * 32;
    const int k0 = blockIdx.y * 64;
    const int t  = threadIdx.x;
    const int tm = t & 31;
    const int tn = t >> 5;
    const int hb = t >> 3, hk = t & 7;
    const int wj = t >> 3, wk = t & 7;

    float4 hv[4], wv;
    #pragma unroll
    for (int r = 0; r < 4; ++r)
        hv[r] = *(const float4*)(h + (hb + 32 * r) * RNN + k0 + hk * 4);
    wv = *(const float4*)(W + (n0 + wj) * RNN + k0 + wk * 4);

    #pragma unroll
    for (int r = 0; r < 4; ++r) {
        h_s[hk*4+0][hb + 32*r] = hv[r].x; h_s[hk*4+1][hb + 32*r] = hv[r].y;
        h_s[hk*4+2][hb + 32*r] = hv[r].z; h_s[hk*4+3][hb + 32*r] = hv[r].w;
    }
    w_s[wk*4+0][wj] = wv.x; w_s[wk*4+1][wj] = wv.y;
    w_s[wk*4+2][wj] = wv.z; w_s[wk*4+3][wj] = wv.w;
    __syncthreads();

    float4 hv2[4], wv2;
    #pragma unroll
    for (int r = 0; r < 4; ++r)
        hv2[r] = *(const float4*)(h + (hb + 32 * r) * RNN + k0 + 32 + hk * 4);
    wv2 = *(const float4*)(W + (n0 + wj) * RNN + k0 + 32 + wk * 4);

    float acc[4][4] = {};
    #pragma unroll 8
    for (int k = 0; k < 32; ++k) {
        float a0 = h_s[k][tm],      a1 = h_s[k][tm + 32],
              a2 = h_s[k][tm + 64], a3 = h_s[k][tm + 96];
        float b0 = w_s[k][tn],      b1 = w_s[k][tn + 8],
              b2 = w_s[k][tn + 16], b3 = w_s[k][tn + 24];
        acc[0][0] += a0*b0; acc[0][1] += a0*b1; acc[0][2] += a0*b2; acc[0][3] += a0*b3;
        acc[1][0] += a1*b0; acc[1][1] += a1*b1; acc[1][2] += a1*b2; acc[1][3] += a1*b3;
        acc[2][0] += a2*b0; acc[2][1] += a2*b1; acc[2][2] += a2*b2; acc[2][3] += a2*b3;
        acc[3][0] += a3*b0; acc[3][1] += a3*b1; acc[3][2] += a3*b2; acc[3][3] += a3*b3;
    }
    __syncthreads();

    #pragma unroll
    for (int r = 0; r < 4; ++r) {
        h_s[hk*4+0][hb + 32*r] = hv2[r].x; h_s[hk*4+1][hb + 32*r] = hv2[r].y;
        h_s[hk*4+2][hb + 32*r] = hv2[r].z; h_s[hk*4+3][hb + 32*r] = hv2[r].w;
    }
    w_s[wk*4+0][wj] = wv2.x; w_s[wk*4+1][wj] = wv2.y;
    w_s[wk*4+2][wj] = wv2.z; w_s[wk*4+3][wj] = wv2.w;
    __syncthreads();

    #pragma unroll 8
    for (int k = 0; k < 32; ++k) {
        float a0 = h_s[k][tm],      a1 = h_s[k][tm + 32],
              a2 = h_s[k][tm + 64], a3 = h_s[k][tm + 96];
        float b0 = w_s[k][tn],      b1 = w_s[k][tn + 8],
              b2 = w_s[k][tn + 16], b3 = w_s[k][tn + 24];
        acc[0][0] += a0*b0; acc[0][1] += a0*b1; acc[0][2] += a0*b2; acc[0][3] += a0*b3;
        acc[1][0] += a1*b0; acc[1][1] += a1*b1; acc[1][2] += a1*b2; acc[1][3] += a1*b3;
        acc[2][0] += a2*b0; acc[2][1] += a2*b1; acc[2][2] += a2*b2; acc[2][3] += a2*b3;
        acc[3][0] += a3*b0; acc[3][1] += a3*b1; acc[3][2] += a3*b2; acc[3][3] += a3*b3;
    }

    float* outp = g_part + blockIdx.y * (HID * BS);
    #pragma unroll
    for (int j = 0; j < 4; ++j)
        #pragma unroll
        for (int i = 0; i < 4; ++i)
            outp[(n0 + tn + 8*j) * BS + tm + 32*i] = acc[i][j];

    // ---- fused reduce tail: last block of this n-tile sums 16 chunks ----
    __threadfence();
    __syncthreads();
    if (t == 0) lastFlag = (atomicAdd(&g_cntn[blockIdx.x], 1) == 15);
    __syncthreads();
    if (!lastFlag) return;

    const float4* p4 = (const float4*)g_part;
    #pragma unroll
    for (int r = 0; r < 4; ++r) {
        int cell = t + 256 * r;       // [32 n][32 b-float4]
        int nn = cell >> 5;
        int bq = cell & 31;
        float bias = b_h2att[n0 + nn];
        float4 s = make_float4(bias, bias, bias, bias);
        #pragma unroll
        for (int c = 0; c < KCHUNKS; ++c) {   // fixed order: deterministic
            float4 v = __ldcg(&p4[((size_t)c * HID + n0 + nn) * (BS / 4) + bq]);
            s.x += v.x; s.y += v.y; s.z += v.z; s.w += v.w;
        }
        *(float4*)&g_atth[(n0 + nn) * BS + bq * 4] = s;
    }
    if (t == 0) g_cntn[blockIdx.x] = 0;
}

// ---------------- K2: scores (max-free masked exp) + fused normalize -------
// grid 512 (= 128 b x 4 obj-chunks of 128), 256 threads. |score| <=
// ||w_alpha||_1 ~ 18 -> exp cannot overflow fp32, max pass dropped (validated
// R8). Emits e = mask*exp(score) + deterministic per-chunk psum; the 4th
// block per row scales the 512 e-values by 1/sum. b_alpha cancels.
__global__ __launch_bounds__(256) void scores_kernel(
    const float* __restrict__ att_feats,
    const float* __restrict__ w_alpha,
    const int*   __restrict__ att_masks,
    float*       __restrict__ out)
{
    const int b     = blockIdx.x >> 2;
    const int chunk = blockIdx.x & 3;
    __shared__ float ah[HID];
    __shared__ float wa[HID];
    __shared__ float mf[128];
    __shared__ float wsum[8];
    __shared__ int   lastFlag;
    const int t = threadIdx.x;

    if (t < 128)
        mf[t] = (float)att_masks[b * OBJ + chunk * 128 + t];
    #pragma unroll
    for (int e = 0; e < 2; ++e) {
        int idx = t + 256 * e;
        ah[idx] = g_atth[idx * BS + b];   // L2-resident gather
        wa[idx] = w_alpha[idx];
    }
    __syncthreads();

    const int w = t >> 5, lane = t & 31;
    const float4* base = (const float4*)(att_feats
                         + (size_t)b * OBJ * HID + (size_t)chunk * 128 * HID);
    const float4* ah4  = (const float4*)ah;
    const float4* wa4  = (const float4*)wa;

    float esum = 0.f;   // meaningful on lane 0
    for (int o = w; o < 128; o += 16) {
        const float4* r0 = base + o       * (HID / 4);
        const float4* r1 = base + (o + 8) * (HID / 4);
        float4 f0[4], f1[4];
        #pragma unroll
        for (int i = 0; i < 4; ++i) {
            f0[i] = __ldcs(r0 + lane + 32 * i);
            f1[i] = __ldcs(r1 + lane + 32 * i);
        }
        float s0 = 0.f, s1 = 0.f;
        #pragma unroll
        for (int i = 0; i < 4; ++i) {
            int idx = lane + 32 * i;
            float4 a  = ah4[idx];
            float4 wv = wa4[idx];
            s0 += tanh_fast(f0[i].x + a.x) * wv.x;
            s0 += tanh_fast(f0[i].y + a.y) * wv.y;
            s0 += tanh_fast(f0[i].z + a.z) * wv.z;
            s0 += tanh_fast(f0[i].w + a.w) * wv.w;
            s1 += tanh_fast(f1[i].x + a.x) * wv.x;
            s1 += tanh_fast(f1[i].y + a.y) * wv.y;
            s1 += tanh_fast(f1[i].z + a.z) * wv.z;
            s1 += tanh_fast(f1[i].w + a.w) * wv.w;
        }
        #pragma unroll
        for (int d = 16; d; d >>= 1) {
            s0 += __shfl_xor_sync(0xffffffffu, s0, d);
            s1 += __shfl_xor_sync(0xffffffffu, s1, d);
        }
        if (lane == 0) {
            float e0 = mf[o]     * __expf(s0);
            float e1 = mf[o + 8] * __expf(s1);
            g_e[b * OBJ + chunk * 128 + o]     = e0;
            g_e[b * OBJ + chunk * 128 + o + 8] = e1;
            esum += e0 + e1;
        }
    }

    if (lane == 0) wsum[w] = esum;
    __syncthreads();
    if (t == 0) {
        float p = 0.f;
        #pragma unroll
        for (int i = 0; i < 8; ++i) p += wsum[i];   // fixed order
        g_psum[b * 4 + chunk] = p;
    }

    // ---- fused normalize tail: 4th block of this row scales 512 values ----
    __threadfence();
    __syncthreads();
    if (t == 0) lastFlag = (atomicAdd(&g_cntb[b], 1) == 3);
    __syncthreads();
    if (!lastFlag) return;

    const float inv = 1.f / (__ldcg(&g_psum[b*4+0]) + __ldcg(&g_psum[b*4+1])
                           + __ldcg(&g_psum[b*4+2]) + __ldcg(&g_psum[b*4+3]));
    #pragma unroll
    for (int i = 0; i < 2; ++i) {
        int idx = b * OBJ + t + 256 * i;
        out[idx] = __ldcg(&g_e[idx]) * inv;
    }
    if (t == 0) g_cntb[b] = 0;
}

extern "C" void kernel_launch(void* const* d_in, const int* in_sizes, int n_in,
                              void* d_out, int out_size) {
    const float* h         = (const float*)d_in[0];
    const float* att_feats = (const float*)d_in[1];
    const int*   att_masks = (const int*)  d_in[2];
    const float* W_h2att   = (const float*)d_in[3];
    const float* b_h2att   = (const float*)d_in[4];
    const float* w_alpha   = (const float*)d_in[5];
    // d_in[6] = b_alpha: cancels in softmax, unused.
    float* out = (float*)d_out;

    gemm_kernel<<<dim3(16, 16), 256>>>(h, W_h2att, b_h2att);
    scores_kernel<<<512, 256>>>(att_feats, w_alpha, att_masks, out);
}

// round 10
// speedup vs baseline: 1.1104x; 1.1104x over previous
#include <cuda_runtime.h>
#include <cuda_bf16.h>

#define BS   128
#define OBJ  512
#define RNN  1024
#define HID  512
#define KCHUNKS 32   // k-chunks of 32

// GEMM partials, layout [chunk][hid][bs] -> coalesced stores. 8MB, L2-resident.
__device__ float g_part[KCHUNKS * HID * BS];
// Reduced att_h + bias, layout [hid][bs] (256KB, L2-resident).
__device__ float g_atth[HID * BS];
// Score scratch: [b][obj]
__device__ float g_scores[BS * OBJ];

__device__ __forceinline__ float tanh_fast(float x) {
    float y;
    asm("tanh.approx.f32 %0, %1;" : "=f"(y) : "f"(x));
    return y;
}

// ---------------- GEMM: att_h partials ----------------
// grid (16 n-tiles of 32, 32 k-chunks of 32), 256 threads, single stage,
// front-batched loads (MLP=5/thread). Scalar-LDS microtile (R4-proven:
// h reads conflict-free, w reads warp-uniform broadcast). Coalesced STG
// epilogue. ~3.5 blocks/SM. part[c][n][b] = sum_{k in c} h[b][k]*W[n][k].
__global__ __launch_bounds__(256) void gemm_kernel(
    const float* __restrict__ h, const float* __restrict__ W)
{
    __shared__ float h_s[32][129];   // [k][b], padded
    __shared__ float w_s[32][33];    // [k][j], padded
    const int n0 = blockIdx.x * 32;
    const int k0 = blockIdx.y * 32;
    const int t  = threadIdx.x;
    const int tm = t & 31;    // b rows tm, +32, +64, +96 (lane-varying)
    const int tn = t >> 5;    // n cols tn, +8, +16, +24 (warp-uniform)
    const int hb = t >> 3, hk = t & 7;
    const int wj = t >> 3, wk = t & 7;

    // Front-batch all 5 global loads
    float4 hv[4], wv;
    #pragma unroll
    for (int r = 0; r < 4; ++r)
        hv[r] = *(const float4*)(h + (hb + 32 * r) * RNN + k0 + hk * 4);
    wv = *(const float4*)(W + (n0 + wj) * RNN + k0 + wk * 4);

    #pragma unroll
    for (int r = 0; r < 4; ++r) {
        h_s[hk*4+0][hb + 32*r] = hv[r].x; h_s[hk*4+1][hb + 32*r] = hv[r].y;
        h_s[hk*4+2][hb + 32*r] = hv[r].z; h_s[hk*4+3][hb + 32*r] = hv[r].w;
    }
    w_s[wk*4+0][wj] = wv.x; w_s[wk*4+1][wj] = wv.y;
    w_s[wk*4+2][wj] = wv.z; w_s[wk*4+3][wj] = wv.w;
    __syncthreads();

    float acc[4][4] = {};
    #pragma unroll 8
    for (int k = 0; k < 32; ++k) {
        float a0 = h_s[k][tm],      a1 = h_s[k][tm + 32],
              a2 = h_s[k][tm + 64], a3 = h_s[k][tm + 96];
        float b0 = w_s[k][tn],      b1 = w_s[k][tn + 8],
              b2 = w_s[k][tn + 16], b3 = w_s[k][tn + 24];
        acc[0][0] += a0*b0; acc[0][1] += a0*b1; acc[0][2] += a0*b2; acc[0][3] += a0*b3;
        acc[1][0] += a1*b0; acc[1][1] += a1*b1; acc[1][2] += a1*b2; acc[1][3] += a1*b3;
        acc[2][0] += a2*b0; acc[2][1] += a2*b1; acc[2][2] += a2*b2; acc[2][3] += a2*b3;
        acc[3][0] += a3*b0; acc[3][1] += a3*b1; acc[3][2] += a3*b2; acc[3][3] += a3*b3;
    }

    // Coalesced epilogue: lanes (tm) vary over consecutive b.
    float* outp = g_part + blockIdx.y * (HID * BS);
    #pragma unroll
    for (int j = 0; j < 4; ++j)
        #pragma unroll
        for (int i = 0; i < 4; ++i)
            outp[(n0 + tn + 8*j) * BS + tm + 32*i] = acc[i][j];
}

// ---------------- Reduce: sum partials + bias ----------------
// grid 256 x 256; one (n,b) element per thread, fully coalesced (8MB L2 read).
__global__ __launch_bounds__(256) void reduce_kernel(
    const float* __restrict__ b_h2att)
{
    const int tid = blockIdx.x * 256 + threadIdx.x;   // n*BS + b
    float s = b_h2att[tid >> 7];   // warp-uniform
    #pragma unroll
    for (int c = 0; c < KCHUNKS; ++c)
        s += g_part[c * (HID * BS) + tid];
    g_atth[tid] = s;
}

// ---------------- Scores: tanh + rank-1 dot (R4-proven) ----------------
// grid 512 (= 128 b x 4 obj-chunks of 128), 256 threads. Streams att_feats
// with __ldcs, MLP=8 per warp. b_alpha dropped (cancels in softmax).
__global__ __launch_bounds__(256) void scores_kernel(
    const float* __restrict__ att_feats,
    const float* __restrict__ w_alpha)
{
    const int b     = blockIdx.x >> 2;
    const int chunk = blockIdx.x & 3;
    __shared__ float ah[HID];
    __shared__ float wa[HID];
    const int t = threadIdx.x;

    #pragma unroll
    for (int e = 0; e < 2; ++e) {
        int idx = t + 256 * e;
        ah[idx] = g_atth[idx * BS + b];   // L2-resident gather
        wa[idx] = w_alpha[idx];
    }
    __syncthreads();

    const int w = t >> 5, lane = t & 31;
    const float4* base = (const float4*)(att_feats
                         + (size_t)b * OBJ * HID + (size_t)chunk * 128 * HID);
    const float4* ah4  = (const float4*)ah;
    const float4* wa4  = (const float4*)wa;

    for (int o = w; o < 128; o += 16) {
        const float4* r0 = base + o       * (HID / 4);
        const float4* r1 = base + (o + 8) * (HID / 4);
        float4 f0[4], f1[4];
        #pragma unroll
        for (int i = 0; i < 4; ++i) {
            f0[i] = __ldcs(r0 + lane + 32 * i);
            f1[i] = __ldcs(r1 + lane + 32 * i);
        }
        float s0 = 0.f, s1 = 0.f;
        #pragma unroll
        for (int i = 0; i < 4; ++i) {
            int idx = lane + 32 * i;
            float4 a  = ah4[idx];
            float4 wv = wa4[idx];
            s0 += tanh_fast(f0[i].x + a.x) * wv.x;
            s0 += tanh_fast(f0[i].y + a.y) * wv.y;
            s0 += tanh_fast(f0[i].z + a.z) * wv.z;
            s0 += tanh_fast(f0[i].w + a.w) * wv.w;
            s1 += tanh_fast(f1[i].x + a.x) * wv.x;
            s1 += tanh_fast(f1[i].y + a.y) * wv.y;
            s1 += tanh_fast(f1[i].z + a.z) * wv.z;
            s1 += tanh_fast(f1[i].w + a.w) * wv.w;
        }
        #pragma unroll
        for (int d = 16; d; d >>= 1) {
            s0 += __shfl_xor_sync(0xffffffffu, s0, d);
            s1 += __shfl_xor_sync(0xffffffffu, s1, d);
        }
        if (lane == 0) {
            g_scores[b * OBJ + chunk * 128 + o]     = s0;
            g_scores[b * OBJ + chunk * 128 + o + 8] = s1;
        }
    }
}

// ---------------- Masked softmax (R4-proven) ----------------
// grid 128, 512 threads. softmax->mask->renorm collapses to masked softmax.
__global__ __launch_bounds__(512) void softmax_kernel(
    const int* __restrict__ att_masks, float* __restrict__ out)
{
    const int b = blockIdx.x;
    const int t = threadIdx.x;
    const int w = t >> 5, lane = t & 31;
    __shared__ float red[16];

    float sc = g_scores[b * OBJ + t];

    float v = sc;
    #pragma unroll
    for (int d = 16; d; d >>= 1) v = fmaxf(v, __shfl_xor_sync(0xffffffffu, v, d));
    if (lane == 0) red[w] = v;
    __syncthreads();
    if (w == 0) {
        float m = red[lane & 15];
        #pragma unroll
        for (int d = 8; d; d >>= 1) m = fmaxf(m, __shfl_xor_sync(0xffffffffu, m, d));
        if (lane == 0) red[0] = m;
    }
    __syncthreads();
    const float mx = red[0];

    float m = (float)att_masks[b * OBJ + t];
    float e = m * __expf(sc - mx);
    float s = e;
    #pragma unroll
    for (int d = 16; d; d >>= 1) s += __shfl_xor_sync(0xffffffffu, s, d);
    __syncthreads();
    if (lane == 0) red[w] = s;
    __syncthreads();
    if (w == 0) {
        float z = red[lane & 15];
        #pragma unroll
        for (int d = 8; d; d >>= 1) z += __shfl_xor_sync(0xffffffffu, z, d);
        if (lane == 0) red[0] = z;
    }
    __syncthreads();
    out[b * OBJ + t] = e * (1.f / red[0]);
}

extern "C" void kernel_launch(void* const* d_in, const int* in_sizes, int n_in,
                              void* d_out, int out_size) {
    const float* h         = (const float*)d_in[0];
    const float* att_feats = (const float*)d_in[1];
    const int*   att_masks = (const int*)  d_in[2];
    const float* W_h2att   = (const float*)d_in[3];
    const float* b_h2att   = (const float*)d_in[4];
    const float* w_alpha   = (const float*)d_in[5];
    // d_in[6] = b_alpha: cancels in softmax, unused.
    float* out = (float*)d_out;

    gemm_kernel<<<dim3(16, 32), 256>>>(h, W_h2att);
    reduce_kernel<<<256, 256>>>(b_h2att);
    scores_kernel<<<512, 256>>>(att_feats, w_alpha);
    softmax_kernel<<<BS, 512>>>(att_masks, out);
}

// round 11
// speedup vs baseline: 1.1722x; 1.0557x over previous
#include <cuda_runtime.h>
#include <cuda_bf16.h>

#define BS   128
#define OBJ  512
#define RNN  1024
#define HID  512
#define KCHUNKS 16   // k-chunks of 64

// GEMM partials, layout [chunk][hid][bs] -> coalesced stores. 4MB, L2-resident.
__device__ float g_part[KCHUNKS * HID * BS];
// Reduced att_h + bias, layout [hid][bs] (256KB, L2-resident).
__device__ float g_atth[HID * BS];
// Score scratch: [b][obj]
__device__ float g_scores[BS * OBJ];

__device__ __forceinline__ float tanh_fast(float x) {
    float y;
    asm("tanh.approx.f32 %0, %1;" : "=f"(y) : "f"(x));
    return y;
}

// ---------------- GEMM: att_h partials ----------------
// grid (8 n-tiles of 64, 16 k-chunks of 64) = 128 blocks = ONE wave.
// 256 threads; tile 128b x 64n; per-thread 4b x 8n = 32 acc.
// Inner iter: 4 LDS.32 (h) + 2 uniform LDS.128 (w) + 32 FFMA.
// 2 pipelined k-stages of 32. part[c][n][b] = sum_{k in c} h[b][k]*W[n][k].
__global__ __launch_bounds__(256) void gemm_kernel(
    const float* __restrict__ h, const float* __restrict__ W)
{
    __shared__ float h_s[32][129];   // [k][b]
    __shared__ float w_s[32][68];    // [k][n], pitch 68 (16B-aligned, STS 4-way only at staging)
    const int n0 = blockIdx.x * 64;
    const int k0 = blockIdx.y * 64;
    const int t  = threadIdx.x;
    const int tm = t & 31;    // b rows tm, +32, +64, +96 (lane-varying)
    const int tn = t >> 5;    // warp id: n cols 8*tn .. 8*tn+7 (warp-uniform)
    const int hb = t >> 3, hk = t & 7;   // h staging: 4 rows hb+32r, slot hk
    const int wr = t >> 3, wk = t & 7;   // W staging: rows wr, wr+32, slot wk

    // ---- stage 1 loads (k0) ----
    float4 hv[4], wv[2];
    #pragma unroll
    for (int r = 0; r < 4; ++r)
        hv[r] = *(const float4*)(h + (hb + 32 * r) * RNN + k0 + hk * 4);
    #pragma unroll
    for (int r = 0; r < 2; ++r)
        wv[r] = *(const float4*)(W + (n0 + wr + 32 * r) * RNN + k0 + wk * 4);

    #pragma unroll
    for (int r = 0; r < 4; ++r) {
        h_s[hk*4+0][hb + 32*r] = hv[r].x; h_s[hk*4+1][hb + 32*r] = hv[r].y;
        h_s[hk*4+2][hb + 32*r] = hv[r].z; h_s[hk*4+3][hb + 32*r] = hv[r].w;
    }
    #pragma unroll
    for (int r = 0; r < 2; ++r) {
        w_s[wk*4+0][wr + 32*r] = wv[r].x; w_s[wk*4+1][wr + 32*r] = wv[r].y;
        w_s[wk*4+2][wr + 32*r] = wv[r].z; w_s[wk*4+3][wr + 32*r] = wv[r].w;
    }
    __syncthreads();

    // ---- stage 2 loads issued now, consumed after stage-1 compute ----
    float4 hv2[4], wv2[2];
    #pragma unroll
    for (int r = 0; r < 4; ++r)
        hv2[r] = *(const float4*)(h + (hb + 32 * r) * RNN + k0 + 32 + hk * 4);
    #pragma unroll
    for (int r = 0; r < 2; ++r)
        wv2[r] = *(const float4*)(W + (n0 + wr + 32 * r) * RNN + k0 + 32 + wk * 4);

    float acc[4][8] = {};   // [b_comp][n_comp]
    #pragma unroll 4
    for (int k = 0; k < 32; ++k) {
        float a0 = h_s[k][tm],      a1 = h_s[k][tm + 32],
              a2 = h_s[k][tm + 64], a3 = h_s[k][tm + 96];
        float4 b0 = *(const float4*)&w_s[k][tn * 8];       // uniform LDS.128
        float4 b1 = *(const float4*)&w_s[k][tn * 8 + 4];
        float bb[8] = {b0.x, b0.y, b0.z, b0.w, b1.x, b1.y, b1.z, b1.w};
        #pragma unroll
        for (int j = 0; j < 8; ++j) {
            acc[0][j] += a0 * bb[j];
            acc[1][j] += a1 * bb[j];
            acc[2][j] += a2 * bb[j];
            acc[3][j] += a3 * bb[j];
        }
    }
    __syncthreads();

    #pragma unroll
    for (int r = 0; r < 4; ++r) {
        h_s[hk*4+0][hb + 32*r] = hv2[r].x; h_s[hk*4+1][hb + 32*r] = hv2[r].y;
        h_s[hk*4+2][hb + 32*r] = hv2[r].z; h_s[hk*4+3][hb + 32*r] = hv2[r].w;
    }
    #pragma unroll
    for (int r = 0; r < 2; ++r) {
        w_s[wk*4+0][wr + 32*r] = wv2[r].x; w_s[wk*4+1][wr + 32*r] = wv2[r].y;
        w_s[wk*4+2][wr + 32*r] = wv2[r].z; w_s[wk*4+3][wr + 32*r] = wv2[r].w;
    }
    __syncthreads();

    #pragma unroll 4
    for (int k = 0; k < 32; ++k) {
        float a0 = h_s[k][tm],      a1 = h_s[k][tm + 32],
              a2 = h_s[k][tm + 64], a3 = h_s[k][tm + 96];
        float4 b0 = *(const float4*)&w_s[k][tn * 8];
        float4 b1 = *(const float4*)&w_s[k][tn * 8 + 4];
        float bb[8] = {b0.x, b0.y, b0.z, b0.w, b1.x, b1.y, b1.z, b1.w};
        #pragma unroll
        for (int j = 0; j < 8; ++j) {
            acc[0][j] += a0 * bb[j];
            acc[1][j] += a1 * bb[j];
            acc[2][j] += a2 * bb[j];
            acc[3][j] += a3 * bb[j];
        }
    }

    // Coalesced epilogue: per (j), lanes write consecutive b.
    float* outp = g_part + blockIdx.y * (HID * BS);
    #pragma unroll
    for (int j = 0; j < 8; ++j)
        #pragma unroll
        for (int i = 0; i < 4; ++i)
            outp[(n0 + tn * 8 + j) * BS + tm + 32*i] = acc[i][j];
}

// ---------------- Reduce: sum partials + bias (R4-proven) ----------------
__global__ __launch_bounds__(256) void reduce_kernel(
    const float* __restrict__ b_h2att)
{
    const int tid = blockIdx.x * 256 + threadIdx.x;   // n*BS + b
    float s = b_h2att[tid >> 7];
    #pragma unroll
    for (int c = 0; c < KCHUNKS; ++c)
        s += g_part[c * (HID * BS) + tid];
    g_atth[tid] = s;
}

// ---------------- Scores: tanh + rank-1 dot (R4-proven) ----------------
__global__ __launch_bounds__(256) void scores_kernel(
    const float* __restrict__ att_feats,
    const float* __restrict__ w_alpha)
{
    const int b     = blockIdx.x >> 2;
    const int chunk = blockIdx.x & 3;
    __shared__ float ah[HID];
    __shared__ float wa[HID];
    const int t = threadIdx.x;

    #pragma unroll
    for (int e = 0; e < 2; ++e) {
        int idx = t + 256 * e;
        ah[idx] = g_atth[idx * BS + b];   // L2-resident gather
        wa[idx] = w_alpha[idx];
    }
    __syncthreads();

    const int w = t >> 5, lane = t & 31;
    const float4* base = (const float4*)(att_feats
                         + (size_t)b * OBJ * HID + (size_t)chunk * 128 * HID);
    const float4* ah4  = (const float4*)ah;
    const float4* wa4  = (const float4*)wa;

    for (int o = w; o < 128; o += 16) {
        const float4* r0 = base + o       * (HID / 4);
        const float4* r1 = base + (o + 8) * (HID / 4);
        float4 f0[4], f1[4];
        #pragma unroll
        for (int i = 0; i < 4; ++i) {
            f0[i] = __ldcs(r0 + lane + 32 * i);
            f1[i] = __ldcs(r1 + lane + 32 * i);
        }
        float s0 = 0.f, s1 = 0.f;
        #pragma unroll
        for (int i = 0; i < 4; ++i) {
            int idx = lane + 32 * i;
            float4 a  = ah4[idx];
            float4 wv = wa4[idx];
            s0 += tanh_fast(f0[i].x + a.x) * wv.x;
            s0 += tanh_fast(f0[i].y + a.y) * wv.y;
            s0 += tanh_fast(f0[i].z + a.z) * wv.z;
            s0 += tanh_fast(f0[i].w + a.w) * wv.w;
            s1 += tanh_fast(f1[i].x + a.x) * wv.x;
            s1 += tanh_fast(f1[i].y + a.y) * wv.y;
            s1 += tanh_fast(f1[i].z + a.z) * wv.z;
            s1 += tanh_fast(f1[i].w + a.w) * wv.w;
        }
        #pragma unroll
        for (int d = 16; d; d >>= 1) {
            s0 += __shfl_xor_sync(0xffffffffu, s0, d);
            s1 += __shfl_xor_sync(0xffffffffu, s1, d);
        }
        if (lane == 0) {
            g_scores[b * OBJ + chunk * 128 + o]     = s0;
            g_scores[b * OBJ + chunk * 128 + o + 8] = s1;
        }
    }
}

// ---------------- Masked softmax (R4-proven) ----------------
__global__ __launch_bounds__(512) void softmax_kernel(
    const int* __restrict__ att_masks, float* __restrict__ out)
{
    const int b = blockIdx.x;
    const int t = threadIdx.x;
    const int w = t >> 5, lane = t & 31;
    __shared__ float red[16];

    float sc = g_scores[b * OBJ + t];

    float v = sc;
    #pragma unroll
    for (int d = 16; d; d >>= 1) v = fmaxf(v, __shfl_xor_sync(0xffffffffu, v, d));
    if (lane == 0) red[w] = v;
    __syncthreads();
    if (w == 0) {
        float m = red[lane & 15];
        #pragma unroll
        for (int d = 8; d; d >>= 1) m = fmaxf(m, __shfl_xor_sync(0xffffffffu, m, d));
        if (lane == 0) red[0] = m;
    }
    __syncthreads();
    const float mx = red[0];

    float m = (float)att_masks[b * OBJ + t];
    float e = m * __expf(sc - mx);
    float s = e;
    #pragma unroll
    for (int d = 16; d; d >>= 1) s += __shfl_xor_sync(0xffffffffu, s, d);
    __syncthreads();
    if (lane == 0) red[w] = s;
    __syncthreads();
    if (w == 0) {
        float z = red[lane & 15];
        #pragma unroll
        for (int d = 8; d; d >>= 1) z += __shfl_xor_sync(0xffffffffu, z, d);
        if (lane == 0) red[0] = z;
    }
    __syncthreads();
    out[b * OBJ + t] = e * (1.f / red[0]);
}

extern "C" void kernel_launch(void* const* d_in, const int* in_sizes, int n_in,
                              void* d_out, int out_size) {
    const float* h         = (const float*)d_in[0];
    const float* att_feats = (const float*)d_in[1];
    const int*   att_masks = (const int*)  d_in[2];
    const float* W_h2att   = (const float*)d_in[3];
    const float* b_h2att   = (const float*)d_in[4];
    const float* w_alpha   = (const float*)d_in[5];
    // d_in[6] = b_alpha: cancels in softmax, unused.
    float* out = (float*)d_out;

    gemm_kernel<<<dim3(8, 16), 256>>>(h, W_h2att);
    reduce_kernel<<<256, 256>>>(b_h2att);
    scores_kernel<<<512, 256>>>(att_feats, w_alpha);
    softmax_kernel<<<BS, 512>>>(att_masks, out);
}